// round 15
// baseline (speedup 1.0000x reference)
#include <cuda_runtime.h>
#include <cuda_fp16.h>
#include <math.h>
#include <cstdint>

// ============================================================================
// Round 15: out = s_in @ Wfold + bfold (algebraic collapse, R2 derivation).
// R14 (best: 24.9us kernel) with two memory-pipeline changes ONLY:
//  - 4-stage prologue + cp.async.wait_group 4 (4 stages in flight per warp)
//  - A loads carry .L2::256B prefetch hint (adjacent 128B chunk pulled early)
// Stage = 16 rows x 128B full lines, XOR-swizzled; fragment-major W in smem;
// fp16 m16n8k16; 16-row warp batches via atomic scheduler. rel_err must be
// bit-identical to R14 (2.9e-4).
// ============================================================================

#define EPS_F 1e-6f

__device__ __half g_Wh[16384];    // fragment-major f16 W (256k x 64n)
__device__ float g_bf[64];
__device__ int g_ctr;

// ---------------- prep: fold Wv over heads, f16-round, scatter --------------
// actual k = c*16 + kq*4 + s*2 + w  <->  hw col (kq*2 + s*8 + w) of step c
__global__ void prep_kernel(const float* __restrict__ Wv,
                            const float* __restrict__ bv, float nf) {
    const float scale = nf / (8.f * (nf + EPS_F));
    const int t = threadIdx.x;                 // 256
    const int k = blockIdx.x * 4 + (t >> 6);   // 0..255
    const int n = t & 63;
    if (blockIdx.x == 0 && t == 0) g_ctr = 0;

    float s = 0.f;
#pragma unroll
    for (int h = 0; h < 8; h++) s += Wv[k * 512 + h * 64 + n];
    float wf = s * scale;

    const int c  = k >> 4;
    const int r  = k & 15;
    const int kq = r >> 2;
    const int s2 = (r >> 1) & 1;
    const int w  = k & 1;
    const int j  = n >> 3;
    const int nn = n & 7;
    const int lane = nn * 4 + kq;
    g_Wh[((((c * 8 + j) * 32) + lane) * 2 + s2) * 2 + w] = __float2half_rn(wf);

    if (k == 0) {
        float b = 0.f;
#pragma unroll
        for (int h = 0; h < 8; h++) b += bv[h * 64 + n];
        g_bf[n] = b * scale;
    }
}

// ---------------- helpers ---------------------------------------------------
#define PACK_F16X2(d, hi, lo) \
    asm("cvt.rn.f16x2.f32 %0, %1, %2;" : "=r"(d) : "f"(hi), "f"(lo))

#define MMA_F16(c, a0, a1, a2, a3, b0, b1)                                      \
    asm volatile(                                                               \
        "mma.sync.aligned.m16n8k16.row.col.f32.f16.f16.f32 "                    \
        "{%0,%1,%2,%3}, {%4,%5,%6,%7}, {%8,%9}, {%0,%1,%2,%3};"                 \
        : "+f"((c)[0]), "+f"((c)[1]), "+f"((c)[2]), "+f"((c)[3])                \
        : "r"(a0), "r"(a1), "r"(a2), "r"(a3), "r"(b0), "r"(b1))

#define CP_ASYNC16(dst, src)                                                    \
    asm volatile("cp.async.cg.shared.global [%0], [%1], 16;"                    \
                 :: "r"(dst), "l"(src) : "memory")
// A-stream variant: prefetch the 256B region (adjacent 128B chunk of the row)
#define CP_ASYNC16_PF(dst, src)                                                 \
    asm volatile("cp.async.cg.shared.global.L2::256B [%0], [%1], 16;"           \
                 :: "r"(dst), "l"(src) : "memory")
#define CP_COMMIT()  asm volatile("cp.async.commit_group;" ::: "memory")
#define CP_WAIT(n)   asm volatile("cp.async.wait_group %0;" :: "n"(n) : "memory")

__device__ __forceinline__ uint32_t smem_u32(const void* p) {
    uint32_t a;
    asm("{ .reg .u64 t; cvta.to.shared.u64 t, %1; cvt.u32.u64 %0, t; }"
        : "=r"(a) : "l"(p));
    return a;
}

#define NCTA 296
#define NSTG 5
// smem u32 layout: [0..8191] W frags | [8192..8255] bias | rings 10KB/warp
#define RING0_U32 8256
#define SMEM_U32  (RING0_U32 + 8 * (NSTG * 512))   // 28736 u32 = 114944 B

// ---------------- main persistent GEMM: [M,256] @ [256,64] ------------------
// 8 warps; 16-row warp batches; stage = 16 rows x 128B (2 k16-chunks).
__global__ __launch_bounds__(256, 2)
void mma_gemm(const float* __restrict__ A, float* __restrict__ C,
              int M, int NB) {
    extern __shared__ uint32_t sm[];
    const uint32_t sb = smem_u32(sm);

    const int t = threadIdx.x;
    const int wid = t >> 5;
    const int lane = t & 31;
    const int g  = lane >> 2;     // consumer row group 0..7
    const int kq = lane & 3;      // consumer k quad
    const int rof = lane >> 3;    // loader row-in-quad 0..3
    const int seg = lane & 7;     // loader 16B segment 0..7

    // loader per-lane constants
    const int swz = seg ^ ((rof & 1) << 2);
    const uint32_t dst_const = (uint32_t)(rof * 128 + swz * 16);
    // consumer per-lane byte offsets within a stage (sub = 0,1)
    const uint32_t cons0 = (uint32_t)(g * 128 + (((0 * 4 + kq) ^ ((g & 1) * 4)) * 16));
    const uint32_t cons1 = (uint32_t)(g * 128 + (((1 * 4 + kq) ^ ((g & 1) * 4)) * 16));

    const uint32_t ringb = sb + RING0_U32 * 4 + wid * (NSTG * 2048);
    const char* ringc = (const char*)sm + RING0_U32 * 4 + wid * (NSTG * 2048);

#define SETUP_PTR(p, base)                                                      \
    const float* p = A + (size_t)min((base) + rof, M - 1) * 256 + seg * 4

#define LOAD_STAGE(p, c2, st) do {                                              \
        uint32_t d_ = ringb + (uint32_t)(st) * 2048 + dst_const;                \
        const float* s_ = (p) + (c2) * 32;                                      \
        CP_ASYNC16_PF(d_,        s_);                                           \
        CP_ASYNC16_PF(d_ + 512,  s_ + 1024);                                    \
        CP_ASYNC16_PF(d_ + 1024, s_ + 2048);                                    \
        CP_ASYNC16_PF(d_ + 1536, s_ + 3072);                                    \
    } while (0)

    // ---- 1) grab first batch + 4-stage A prologue ----
    int b;
    if (lane == 0) b = atomicAdd(&g_ctr, 1);
    b = __shfl_sync(0xffffffffu, b, 0);
    const bool have = (b < NB);

    if (have) {
        SETUP_PTR(i0, b * 16);
        LOAD_STAGE(i0, 0, 0); CP_COMMIT();
        LOAD_STAGE(i0, 1, 1); CP_COMMIT();
        LOAD_STAGE(i0, 2, 2); CP_COMMIT();
        LOAD_STAGE(i0, 3, 3); CP_COMMIT();
    } else {
        CP_COMMIT(); CP_COMMIT(); CP_COMMIT(); CP_COMMIT();
    }

    // ---- 2) stage W (32 KB, L2-hot) + bias ----
    {
        uint32_t dst = sb + t * 16;
        const char* src = (const char*)g_Wh + t * 16;
#pragma unroll
        for (int i = 0; i < 8; i++)
            CP_ASYNC16(dst + i * 4096, src + i * 4096);
        CP_COMMIT();
    }
    if (t < 64) ((float*)(sm + 8192))[t] = g_bf[t];
    CP_WAIT(0);
    __syncthreads();

    const uint2* Wp = ((const uint2*)sm) + lane;
    const float* bias_s = (const float*)(sm + 8192);

    // ---- 3) mainloop: 8 stages per batch, rolling 5-slot ring, depth 4 ----
    if (have) {
        SETUP_PTR(s0, b * 16);
        const float* cp_ = s0;
        int ldst = 4;   // next load slot (prologue used 0..3)
        int rdst = 0;   // next read slot

        for (;;) {
            int bn = NB;
            const float* np_ = cp_;

            float acc[8][4];
#pragma unroll
            for (int j = 0; j < 8; j++)
#pragma unroll
                for (int i = 0; i < 4; i++) acc[j][i] = 0.f;

#pragma unroll
            for (int s = 0; s < 8; s++) {
                if (s == 2) {
                    if (lane == 0) bn = atomicAdd(&g_ctr, 1);
                    bn = __shfl_sync(0xffffffffu, bn, 0);
                }
                if (s == 3 && bn < NB) {
                    SETUP_PTR(t0, bn * 16);
                    np_ = t0;
                }
                if (s < 4) {
                    LOAD_STAGE(cp_, s + 4, ldst);
                    if (++ldst == NSTG) ldst = 0;
                } else if (bn < NB) {
                    LOAD_STAGE(np_, s - 4, ldst);
                    if (++ldst == NSTG) ldst = 0;
                }
                CP_COMMIT();
                CP_WAIT(4);

                const int st = rdst;
                if (++rdst == NSTG) rdst = 0;
                const char* stp = ringc + st * 2048;

                // sub = 0  (k-chunk c = s*2)
                {
                    float4 q0 = *(const float4*)(stp + cons0);
                    float4 q1 = *(const float4*)(stp + cons0 + 1024);
                    uint32_t a0, a1, a2, a3;
                    PACK_F16X2(a0, q0.y, q0.x); PACK_F16X2(a1, q1.y, q1.x);
                    PACK_F16X2(a2, q0.w, q0.z); PACK_F16X2(a3, q1.w, q1.z);
#pragma unroll
                    for (int j = 0; j < 8; j++) {
                        uint2 w2 = Wp[((s * 2 + 0) * 8 + j) * 32];
                        MMA_F16(acc[j], a0, a1, a2, a3, w2.x, w2.y);
                    }
                }
                // sub = 1  (k-chunk c = s*2 + 1)
                {
                    float4 q0 = *(const float4*)(stp + cons1);
                    float4 q1 = *(const float4*)(stp + cons1 + 1024);
                    uint32_t a0, a1, a2, a3;
                    PACK_F16X2(a0, q0.y, q0.x); PACK_F16X2(a1, q1.y, q1.x);
                    PACK_F16X2(a2, q0.w, q0.z); PACK_F16X2(a3, q1.w, q1.z);
#pragma unroll
                    for (int j = 0; j < 8; j++) {
                        uint2 w2 = Wp[((s * 2 + 1) * 8 + j) * 32];
                        MMA_F16(acc[j], a0, a1, a2, a3, w2.x, w2.y);
                    }
                }
            }

            // epilogue: bias + store (rows b*16+g, +8; cols j*8 + kq*2, +1)
            const int r0 = b * 16 + g;
            const int r1 = r0 + 8;
#pragma unroll
            for (int j = 0; j < 8; j++) {
                int col = j * 8 + kq * 2;
                float2 bb = *(const float2*)(bias_s + col);
                if (r0 < M)
                    *(float2*)(C + (size_t)r0 * 64 + col) =
                        make_float2(acc[j][0] + bb.x, acc[j][1] + bb.y);
                if (r1 < M)
                    *(float2*)(C + (size_t)r1 * 64 + col) =
                        make_float2(acc[j][2] + bb.x, acc[j][3] + bb.y);
            }

            if (bn >= NB) break;
            b = bn;
            cp_ = np_;
        }
    }
#undef LOAD_STAGE
#undef SETUP_PTR
}

// ---------------- launch ----------------------------------------------------
extern "C" void kernel_launch(void* const* d_in, const int* in_sizes, int n_in,
                              void* d_out, int out_size) {
    const float* s_in = (const float*)d_in[1];
    const float* Wv   = (const float*)d_in[6];
    const float* bv   = (const float*)d_in[7];
    float* out = (float*)d_out;

    const int M = in_sizes[0] / 256;
    const int NB = (M + 15) / 16;

    prep_kernel<<<64, 256>>>(Wv, bv, (float)M);

    const int SMEM = SMEM_U32 * 4;   // 114944 B -> 2 CTAs/SM
    cudaFuncSetAttribute(mma_gemm,
                         cudaFuncAttributeMaxDynamicSharedMemorySize, SMEM);
    mma_gemm<<<NCTA, 256, SMEM>>>(s_in, out, M, NB);
}

// round 16
// speedup vs baseline: 1.0370x; 1.0370x over previous
#include <cuda_runtime.h>
#include <cuda_fp16.h>
#include <math.h>
#include <cstdint>

// ============================================================================
// Round 16: out = s_in @ Wfold + bfold (algebraic collapse, R2 derivation).
// R15 kernel (best: 24.2us) with ONE change: NCTA 296 -> 262.
//   NB=6250 batches / 2096 warps = 2.982 -> every warp draws <=3 batches
//   (scheduler utilization 99.4% vs 88.0% at 296 CTAs / 2.64 per warp).
// Stage = 16 rows x 128B full lines (XOR swizzle), 5-slot ring wait-depth 4,
// L2::256B prefetch on A, fragment-major W, fp16 m16n8k16, atomic scheduler.
// ============================================================================

#define EPS_F 1e-6f

__device__ __half g_Wh[16384];    // fragment-major f16 W (256k x 64n)
__device__ float g_bf[64];
__device__ int g_ctr;

// ---------------- prep: fold Wv over heads, f16-round, scatter --------------
// actual k = c*16 + kq*4 + s*2 + w  <->  hw col (kq*2 + s*8 + w) of step c
__global__ void prep_kernel(const float* __restrict__ Wv,
                            const float* __restrict__ bv, float nf) {
    const float scale = nf / (8.f * (nf + EPS_F));
    const int t = threadIdx.x;                 // 256
    const int k = blockIdx.x * 4 + (t >> 6);   // 0..255
    const int n = t & 63;
    if (blockIdx.x == 0 && t == 0) g_ctr = 0;

    float s = 0.f;
#pragma unroll
    for (int h = 0; h < 8; h++) s += Wv[k * 512 + h * 64 + n];
    float wf = s * scale;

    const int c  = k >> 4;
    const int r  = k & 15;
    const int kq = r >> 2;
    const int s2 = (r >> 1) & 1;
    const int w  = k & 1;
    const int j  = n >> 3;
    const int nn = n & 7;
    const int lane = nn * 4 + kq;
    g_Wh[((((c * 8 + j) * 32) + lane) * 2 + s2) * 2 + w] = __float2half_rn(wf);

    if (k == 0) {
        float b = 0.f;
#pragma unroll
        for (int h = 0; h < 8; h++) b += bv[h * 64 + n];
        g_bf[n] = b * scale;
    }
}

// ---------------- helpers ---------------------------------------------------
#define PACK_F16X2(d, hi, lo) \
    asm("cvt.rn.f16x2.f32 %0, %1, %2;" : "=r"(d) : "f"(hi), "f"(lo))

#define MMA_F16(c, a0, a1, a2, a3, b0, b1)                                      \
    asm volatile(                                                               \
        "mma.sync.aligned.m16n8k16.row.col.f32.f16.f16.f32 "                    \
        "{%0,%1,%2,%3}, {%4,%5,%6,%7}, {%8,%9}, {%0,%1,%2,%3};"                 \
        : "+f"((c)[0]), "+f"((c)[1]), "+f"((c)[2]), "+f"((c)[3])                \
        : "r"(a0), "r"(a1), "r"(a2), "r"(a3), "r"(b0), "r"(b1))

#define CP_ASYNC16(dst, src)                                                    \
    asm volatile("cp.async.cg.shared.global [%0], [%1], 16;"                    \
                 :: "r"(dst), "l"(src) : "memory")
// A-stream variant: prefetch the 256B region (adjacent 128B chunk of the row)
#define CP_ASYNC16_PF(dst, src)                                                 \
    asm volatile("cp.async.cg.shared.global.L2::256B [%0], [%1], 16;"           \
                 :: "r"(dst), "l"(src) : "memory")
#define CP_COMMIT()  asm volatile("cp.async.commit_group;" ::: "memory")
#define CP_WAIT(n)   asm volatile("cp.async.wait_group %0;" :: "n"(n) : "memory")

__device__ __forceinline__ uint32_t smem_u32(const void* p) {
    uint32_t a;
    asm("{ .reg .u64 t; cvta.to.shared.u64 t, %1; cvt.u32.u64 %0, t; }"
        : "=r"(a) : "l"(p));
    return a;
}

#define NCTA 262
#define NSTG 5
// smem u32 layout: [0..8191] W frags | [8192..8255] bias | rings 10KB/warp
#define RING0_U32 8256
#define SMEM_U32  (RING0_U32 + 8 * (NSTG * 512))   // 28736 u32 = 114944 B

// ---------------- main persistent GEMM: [M,256] @ [256,64] ------------------
// 8 warps; 16-row warp batches; stage = 16 rows x 128B (2 k16-chunks).
__global__ __launch_bounds__(256, 2)
void mma_gemm(const float* __restrict__ A, float* __restrict__ C,
              int M, int NB) {
    extern __shared__ uint32_t sm[];
    const uint32_t sb = smem_u32(sm);

    const int t = threadIdx.x;
    const int wid = t >> 5;
    const int lane = t & 31;
    const int g  = lane >> 2;     // consumer row group 0..7
    const int kq = lane & 3;      // consumer k quad
    const int rof = lane >> 3;    // loader row-in-quad 0..3
    const int seg = lane & 7;     // loader 16B segment 0..7

    // loader per-lane constants
    const int swz = seg ^ ((rof & 1) << 2);
    const uint32_t dst_const = (uint32_t)(rof * 128 + swz * 16);
    // consumer per-lane byte offsets within a stage (sub = 0,1)
    const uint32_t cons0 = (uint32_t)(g * 128 + (((0 * 4 + kq) ^ ((g & 1) * 4)) * 16));
    const uint32_t cons1 = (uint32_t)(g * 128 + (((1 * 4 + kq) ^ ((g & 1) * 4)) * 16));

    const uint32_t ringb = sb + RING0_U32 * 4 + wid * (NSTG * 2048);
    const char* ringc = (const char*)sm + RING0_U32 * 4 + wid * (NSTG * 2048);

#define SETUP_PTR(p, base)                                                      \
    const float* p = A + (size_t)min((base) + rof, M - 1) * 256 + seg * 4

#define LOAD_STAGE(p, c2, st) do {                                              \
        uint32_t d_ = ringb + (uint32_t)(st) * 2048 + dst_const;                \
        const float* s_ = (p) + (c2) * 32;                                      \
        CP_ASYNC16_PF(d_,        s_);                                           \
        CP_ASYNC16_PF(d_ + 512,  s_ + 1024);                                    \
        CP_ASYNC16_PF(d_ + 1024, s_ + 2048);                                    \
        CP_ASYNC16_PF(d_ + 1536, s_ + 3072);                                    \
    } while (0)

    // ---- 1) grab first batch + 4-stage A prologue ----
    int b;
    if (lane == 0) b = atomicAdd(&g_ctr, 1);
    b = __shfl_sync(0xffffffffu, b, 0);
    const bool have = (b < NB);

    if (have) {
        SETUP_PTR(i0, b * 16);
        LOAD_STAGE(i0, 0, 0); CP_COMMIT();
        LOAD_STAGE(i0, 1, 1); CP_COMMIT();
        LOAD_STAGE(i0, 2, 2); CP_COMMIT();
        LOAD_STAGE(i0, 3, 3); CP_COMMIT();
    } else {
        CP_COMMIT(); CP_COMMIT(); CP_COMMIT(); CP_COMMIT();
    }

    // ---- 2) stage W (32 KB, L2-hot) + bias ----
    {
        uint32_t dst = sb + t * 16;
        const char* src = (const char*)g_Wh + t * 16;
#pragma unroll
        for (int i = 0; i < 8; i++)
            CP_ASYNC16(dst + i * 4096, src + i * 4096);
        CP_COMMIT();
    }
    if (t < 64) ((float*)(sm + 8192))[t] = g_bf[t];
    CP_WAIT(0);
    __syncthreads();

    const uint2* Wp = ((const uint2*)sm) + lane;
    const float* bias_s = (const float*)(sm + 8192);

    // ---- 3) mainloop: 8 stages per batch, rolling 5-slot ring, depth 4 ----
    if (have) {
        SETUP_PTR(s0, b * 16);
        const float* cp_ = s0;
        int ldst = 4;   // next load slot (prologue used 0..3)
        int rdst = 0;   // next read slot

        for (;;) {
            int bn = NB;
            const float* np_ = cp_;

            float acc[8][4];
#pragma unroll
            for (int j = 0; j < 8; j++)
#pragma unroll
                for (int i = 0; i < 4; i++) acc[j][i] = 0.f;

#pragma unroll
            for (int s = 0; s < 8; s++) {
                if (s == 2) {
                    if (lane == 0) bn = atomicAdd(&g_ctr, 1);
                    bn = __shfl_sync(0xffffffffu, bn, 0);
                }
                if (s == 3 && bn < NB) {
                    SETUP_PTR(t0, bn * 16);
                    np_ = t0;
                }
                if (s < 4) {
                    LOAD_STAGE(cp_, s + 4, ldst);
                    if (++ldst == NSTG) ldst = 0;
                } else if (bn < NB) {
                    LOAD_STAGE(np_, s - 4, ldst);
                    if (++ldst == NSTG) ldst = 0;
                }
                CP_COMMIT();
                CP_WAIT(4);

                const int st = rdst;
                if (++rdst == NSTG) rdst = 0;
                const char* stp = ringc + st * 2048;

                // sub = 0  (k-chunk c = s*2)
                {
                    float4 q0 = *(const float4*)(stp + cons0);
                    float4 q1 = *(const float4*)(stp + cons0 + 1024);
                    uint32_t a0, a1, a2, a3;
                    PACK_F16X2(a0, q0.y, q0.x); PACK_F16X2(a1, q1.y, q1.x);
                    PACK_F16X2(a2, q0.w, q0.z); PACK_F16X2(a3, q1.w, q1.z);
#pragma unroll
                    for (int j = 0; j < 8; j++) {
                        uint2 w2 = Wp[((s * 2 + 0) * 8 + j) * 32];
                        MMA_F16(acc[j], a0, a1, a2, a3, w2.x, w2.y);
                    }
                }
                // sub = 1  (k-chunk c = s*2 + 1)
                {
                    float4 q0 = *(const float4*)(stp + cons1);
                    float4 q1 = *(const float4*)(stp + cons1 + 1024);
                    uint32_t a0, a1, a2, a3;
                    PACK_F16X2(a0, q0.y, q0.x); PACK_F16X2(a1, q1.y, q1.x);
                    PACK_F16X2(a2, q0.w, q0.z); PACK_F16X2(a3, q1.w, q1.z);
#pragma unroll
                    for (int j = 0; j < 8; j++) {
                        uint2 w2 = Wp[((s * 2 + 1) * 8 + j) * 32];
                        MMA_F16(acc[j], a0, a1, a2, a3, w2.x, w2.y);
                    }
                }
            }

            // epilogue: bias + store (rows b*16+g, +8; cols j*8 + kq*2, +1)
            const int r0 = b * 16 + g;
            const int r1 = r0 + 8;
#pragma unroll
            for (int j = 0; j < 8; j++) {
                int col = j * 8 + kq * 2;
                float2 bb = *(const float2*)(bias_s + col);
                if (r0 < M)
                    *(float2*)(C + (size_t)r0 * 64 + col) =
                        make_float2(acc[j][0] + bb.x, acc[j][1] + bb.y);
                if (r1 < M)
                    *(float2*)(C + (size_t)r1 * 64 + col) =
                        make_float2(acc[j][2] + bb.x, acc[j][3] + bb.y);
            }

            if (bn >= NB) break;
            b = bn;
            cp_ = np_;
        }
    }
#undef LOAD_STAGE
#undef SETUP_PTR
}

// ---------------- launch ----------------------------------------------------
extern "C" void kernel_launch(void* const* d_in, const int* in_sizes, int n_in,
                              void* d_out, int out_size) {
    const float* s_in = (const float*)d_in[1];
    const float* Wv   = (const float*)d_in[6];
    const float* bv   = (const float*)d_in[7];
    float* out = (float*)d_out;

    const int M = in_sizes[0] / 256;
    const int NB = (M + 15) / 16;

    prep_kernel<<<64, 256>>>(Wv, bv, (float)M);

    const int SMEM = SMEM_U32 * 4;   // 114944 B -> 2 CTAs/SM
    cudaFuncSetAttribute(mma_gemm,
                         cudaFuncAttributeMaxDynamicSharedMemorySize, SMEM);
    mma_gemm<<<NCTA, 256, SMEM>>>(s_in, out, M, NB);
}